// round 17
// baseline (speedup 1.0000x reference)
#include <cuda_runtime.h>
#include <cfloat>
#include <math.h>
#include <stdint.h>

#define NB    8
#define NLQ   512
#define NLK   2048
#define NE    512
#define NH    8
#define NHD   64
#define NTOPK 20
#define FULL  0xffffffffu
#define CAP   64

// Scratch (allocation-free rule: __device__ globals)
__device__ float g_Q[(size_t)NB * NLQ * NE];             // 8 MB
__device__ float g_K[(size_t)NB * NLK * NE];             // 32 MB
__device__ float g_V[(size_t)NB * NLK * NE];             // 32 MB
__device__ float g_S[(size_t)NB * NH * NLQ * NLK];       // 256 MB (also input scratch)
__device__ float g_O[(size_t)NB * NLQ * NE];             // 8 MB
__device__ float g_Wc[4 * 262144];                       // 4 MB converted weights

// scratch offsets inside g_S (floats) for converted q,k,v
#define CQ_OFF 0
#define CK_OFF 2097152
#define CV_OFF 10485760

__device__ __forceinline__ float to_tf32(float x) {
    uint32_t u;
    asm("cvt.rna.tf32.f32 %0, %1;" : "=r"(u) : "f"(x));
    return __uint_as_float(u);
}

__device__ __forceinline__ uint32_t smem_u32(const void* p) {
    return (uint32_t)__cvta_generic_to_shared(p);
}

#define LDSM_X4(R0, R1, R2, R3, ADDR)                                          \
    asm volatile("ldmatrix.sync.aligned.m8n8.x4.shared.b16 {%0,%1,%2,%3}, [%4];" \
                 : "=r"(R0), "=r"(R1), "=r"(R2), "=r"(R3) : "r"(ADDR))

#define MMA_TF32(C, A, B0, B1)                                                  \
    asm volatile("mma.sync.aligned.m16n8k8.row.col.f32.tf32.tf32.f32 "          \
                 "{%0,%1,%2,%3}, {%4,%5,%6,%7}, {%8,%9}, {%0,%1,%2,%3};"        \
                 : "+f"((C)[0]), "+f"((C)[1]), "+f"((C)[2]), "+f"((C)[3])       \
                 : "r"((A)[0]), "r"((A)[1]), "r"((A)[2]), "r"((A)[3]),          \
                   "r"(B0), "r"(B1))

#define CP_ASYNC16(DST, SRC)                                                    \
    asm volatile("cp.async.cg.shared.global [%0], [%1], 16;" :: "r"(DST), "l"(SRC))
#define CP_COMMIT() asm volatile("cp.async.commit_group;" ::: "memory")
#define CP_WAIT1()  asm volatile("cp.async.wait_group 1;"  ::: "memory")
#define CP_WAIT0()  asm volatile("cp.async.wait_group 0;"  ::: "memory")

// ----------------------------------------------------------------------------
// Elementwise tf32 rounding (float4 granularity, streaming)
// ----------------------------------------------------------------------------
__global__ void cvt4(float4* __restrict__ dst, const float4* __restrict__ src, int n4)
{
    const int i = blockIdx.x * 256 + threadIdx.x;
    if (i < n4) {
        float4 t = __ldcs(src + i);
        t.x = to_tf32(t.x); t.y = to_tf32(t.y);
        t.z = to_tf32(t.z); t.w = to_tf32(t.w);
        __stcs(dst + i, t);
    }
}

// ----------------------------------------------------------------------------
// TF32 tensor-core GEMM, inputs PRE-ROUNDED to tf32.
// C = alpha * A @ Bw^T (+bias +resid). 128x128 tile, BK=32, 256 threads,
// warp tile 64x32 (m16n8k8). cp.async 2-stage double buffer: no register
// staging, no cvt, one compute phase per K-tile. Batched via blockIdx.z.
// streamC -> __stcs stores; roundC -> round output to tf32 at store.
// ----------------------------------------------------------------------------
#define STG_F (128 * 36)
#define GEMM_SMEM_BYTES (4 * STG_F * 4)

__global__ __launch_bounds__(256, 2)
void gemm_ca(const float* __restrict__ A, const float* __restrict__ Bw,
             float* __restrict__ C,
             int K, int lda, int ldb, int ldc, float alpha,
             size_t sAb, size_t sAh, size_t sBb, size_t sBh, size_t sCz, int hdiv,
             const float* __restrict__ bias, const float* __restrict__ resid,
             int streamC, int roundC)
{
    extern __shared__ float smp[];
    float* Asb = smp;                 // 2 stages of A: [2][128][36]
    float* Bsb = smp + 2 * STG_F;     // 2 stages of B

    const int tid  = threadIdx.x;
    const int lane = tid & 31;
    const int wid  = tid >> 5;
    const int wm   = wid >> 2;
    const int wn   = wid & 3;
    const int rowBase = blockIdx.y * 128;
    const int colBase = blockIdx.x * 128;

    const int z  = blockIdx.z;
    const int zb = z / hdiv;
    const int zh = z - zb * hdiv;
    A  += (size_t)zb * sAb + (size_t)zh * sAh;
    Bw += (size_t)zb * sBb + (size_t)zh * sBh;
    C  += (size_t)z * sCz;

    // loader coords: 4 x 16B per matrix per tile
    int lrow[4], lcol[4];
    #pragma unroll
    for (int i = 0; i < 4; i++) {
        int f = tid + (i << 8);
        lrow[i] = f >> 3;
        lcol[i] = (f & 7) << 2;
    }
    uint32_t aDst[2][4], bDst[2][4];
    #pragma unroll
    for (int s = 0; s < 2; s++)
        #pragma unroll
        for (int i = 0; i < 4; i++) {
            aDst[s][i] = smem_u32(Asb + s * STG_F + lrow[i] * 36 + lcol[i]);
            bDst[s][i] = smem_u32(Bsb + s * STG_F + lrow[i] * 36 + lcol[i]);
        }

    // fragment addresses per stage
    const int arow = wm * 64 + (lane & 15);
    const int acol = (lane >> 4) << 2;
    const int brow = wn * 32 + ((lane >> 4) << 3) + (lane & 7);
    const int bcol = ((lane >> 3) & 1) << 2;
    uint32_t aAddr[2][4], bAddr[2][2];
    #pragma unroll
    for (int s = 0; s < 2; s++) {
        #pragma unroll
        for (int mi = 0; mi < 4; mi++)
            aAddr[s][mi] = smem_u32(Asb + s * STG_F + (arow + mi * 16) * 36 + acol);
        #pragma unroll
        for (int p = 0; p < 2; p++)
            bAddr[s][p] = smem_u32(Bsb + s * STG_F + (brow + p * 16) * 36 + bcol);
    }

    float acc[4][4][4];
    #pragma unroll
    for (int mi = 0; mi < 4; mi++)
        #pragma unroll
        for (int ni = 0; ni < 4; ni++)
            #pragma unroll
            for (int r = 0; r < 4; r++) acc[mi][ni][r] = 0.f;

    #define ISSUE(S, K0) do {                                                     \
        _Pragma("unroll")                                                          \
        for (int i = 0; i < 4; i++) {                                              \
            const float* srcA = A + (size_t)(rowBase + lrow[i]) * lda + (K0) + lcol[i]; \
            CP_ASYNC16(aDst[S][i], srcA);                                          \
            const float* srcB = Bw + (size_t)(colBase + lrow[i]) * ldb + (K0) + lcol[i]; \
            CP_ASYNC16(bDst[S][i], srcB);                                          \
        }                                                                          \
        CP_COMMIT();                                                               \
    } while (0)

    const int T = K >> 5;
    ISSUE(0, 0);
    if (T > 1) ISSUE(1, 32);

    for (int t = 0; t < T; t++) {
        if (t + 1 < T) CP_WAIT1(); else CP_WAIT0();
        __syncthreads();

        const int s = t & 1;
        #pragma unroll
        for (int ks = 0; ks < 4; ks++) {
            const uint32_t koff = ks * 32;
            uint32_t a[4][4], b[2][4];
            #pragma unroll
            for (int mi = 0; mi < 4; mi++)
                LDSM_X4(a[mi][0], a[mi][1], a[mi][2], a[mi][3], aAddr[s][mi] + koff);
            #pragma unroll
            for (int p = 0; p < 2; p++)
                LDSM_X4(b[p][0], b[p][1], b[p][2], b[p][3], bAddr[s][p] + koff);
            #pragma unroll
            for (int mi = 0; mi < 4; mi++)
                #pragma unroll
                for (int ni = 0; ni < 4; ni++) {
                    const int p = ni >> 1, o = (ni & 1) << 1;
                    MMA_TF32(acc[mi][ni], a[mi], b[p][o], b[p][o + 1]);
                }
        }
        __syncthreads();
        if (t + 2 < T) ISSUE(s, (t + 2) << 5);
    }
    #undef ISSUE

    const int erow = rowBase + wm * 64 + (lane >> 2);
    const int ecol = colBase + wn * 32 + ((lane & 3) << 1);
    #pragma unroll
    for (int mi = 0; mi < 4; mi++) {
        #pragma unroll
        for (int ni = 0; ni < 4; ni++) {
            const int r = erow + mi * 16;
            const int c = ecol + ni * 8;
            float2 add = make_float2(0.f, 0.f);
            if (bias) {
                float2 bb = *reinterpret_cast<const float2*>(bias + c);
                add.x += bb.x; add.y += bb.y;
            }
            float2 v0, v1;
            v0.x = alpha * acc[mi][ni][0] + add.x;
            v0.y = alpha * acc[mi][ni][1] + add.y;
            v1.x = alpha * acc[mi][ni][2] + add.x;
            v1.y = alpha * acc[mi][ni][3] + add.y;
            if (resid) {
                float2 r0 = *reinterpret_cast<const float2*>(resid + (size_t)r * ldc + c);
                float2 r1 = *reinterpret_cast<const float2*>(resid + (size_t)(r + 8) * ldc + c);
                v0.x += r0.x; v0.y += r0.y;
                v1.x += r1.x; v1.y += r1.y;
            }
            if (roundC) {
                v0.x = to_tf32(v0.x); v0.y = to_tf32(v0.y);
                v1.x = to_tf32(v1.x); v1.y = to_tf32(v1.y);
            }
            float2* p0 = reinterpret_cast<float2*>(C + (size_t)r * ldc + c);
            float2* p1 = reinterpret_cast<float2*>(C + (size_t)(r + 8) * ldc + c);
            if (streamC) { __stcs(p0, v0); __stcs(p1, v1); }
            else         { *p0 = v0;       *p1 = v1;       }
        }
    }
}

// ----------------------------------------------------------------------------
// Top-k: 2 warps per score row (32 values/lane), block-shared per-row state.
// (unchanged from round 16, except g_O store rounded to tf32 for out-proj)
// ----------------------------------------------------------------------------
__device__ __forceinline__ uint32_t fkey(float f) {
    uint32_t u = __float_as_uint(f);
    return (u & 0x80000000u) ? ~u : (u | 0x80000000u);
}
__device__ __forceinline__ float fkey_inv(uint32_t k) {
    uint32_t u = (k & 0x80000000u) ? (k ^ 0x80000000u) : ~k;
    return __uint_as_float(u);
}

__device__ __forceinline__ void hist_thresh(const int* h, int lane, int target,
                                            int& B, int& cntAbove)
{
    int c = 0;
    #pragma unroll
    for (int k = 0; k < 8; k++) c += h[lane * 8 + k];
    int S = c;
    #pragma unroll
    for (int off = 1; off < 32; off <<= 1) {
        int o = __shfl_down_sync(FULL, S, off);
        if (lane + off < 32) S += o;
    }
    int Snext = __shfl_down_sync(FULL, S, 1);
    if (lane == 31) Snext = 0;
    const bool isL = (S >= target) && (Snext < target);
    const unsigned ball = __ballot_sync(FULL, isL);
    const int L = __ffs(ball) - 1;
    int myB = 0, myC = 0;
    if (isL) {
        int cum = Snext;
        for (int bb = lane * 8 + 7; bb >= lane * 8; bb--) {
            if (cum + h[bb] >= target) { myB = bb; myC = cum; break; }
            cum += h[bb];
        }
    }
    B        = __shfl_sync(FULL, myB, L);
    cntAbove = __shfl_sync(FULL, myC, L);
}

__global__ __launch_bounds__(256)
void topk_av()
{
    __shared__ int      hist1[4][256];
    __shared__ int      hist2[4][256];
    __shared__ uint32_t candK[4][CAP];
    __shared__ int      candI[4][CAP];
    __shared__ int      cnt[4];
    __shared__ float    mxh[4][2];
    __shared__ float    smh[4][2];
    __shared__ float    topV[4][NTOPK];
    __shared__ int      topIx[4][NTOPK];

    const int tid  = threadIdx.x;
    const int lane = tid & 31;
    const int wid  = tid >> 5;
    const int pair = wid >> 1;
    const int half = wid & 1;
    const int row  = blockIdx.x * 4 + pair;
    const int q    = row & (NLQ - 1);
    const int bh   = row >> 9;
    const int h    = bh & (NH - 1);
    const int b    = bh >> 3;

    const float* s = g_S + (size_t)row * NLK + half * 1024;

    #pragma unroll
    for (int i = 0; i < 4; i++) {
        (&hist1[0][0])[tid + (i << 8)] = 0;
        (&hist2[0][0])[tid + (i << 8)] = 0;
    }
    if (tid < 4) cnt[tid] = 0;

    float v[32];
    #pragma unroll
    for (int i = 0; i < 8; i++) {
        float4 t = __ldcs(reinterpret_cast<const float4*>(s + i * 128 + lane * 4));
        v[i * 4 + 0] = t.x; v[i * 4 + 1] = t.y;
        v[i * 4 + 2] = t.z; v[i * 4 + 3] = t.w;
    }

    float m = v[0];
    #pragma unroll
    for (int i = 1; i < 32; i++) m = fmaxf(m, v[i]);
    #pragma unroll
    for (int off = 16; off > 0; off >>= 1)
        m = fmaxf(m, __shfl_xor_sync(FULL, m, off));
    if (lane == 0) mxh[pair][half] = m;
    __syncthreads();
    m = fmaxf(mxh[pair][0], mxh[pair][1]);

    float ls = 0.f;
    #pragma unroll
    for (int i = 0; i < 32; i++) ls += __expf(v[i] - m);
    #pragma unroll
    for (int off = 16; off > 0; off >>= 1)
        ls += __shfl_xor_sync(FULL, ls, off);
    if (lane == 0) smh[pair][half] = ls;

    #pragma unroll
    for (int i = 0; i < 32; i++) v[i] = __uint_as_float(fkey(v[i]));

    #pragma unroll
    for (int i = 0; i < 32; i++)
        atomicAdd(&hist1[pair][__float_as_uint(v[i]) >> 24], 1);
    __syncthreads();
    const float ssum = smh[pair][0] + smh[pair][1];

    int B1, cnt1;
    hist_thresh(hist1[pair], lane, NTOPK, B1, cnt1);

    #pragma unroll
    for (int i = 0; i < 32; i++) {
        const uint32_t k = __float_as_uint(v[i]);
        if ((k >> 24) == (uint32_t)B1) atomicAdd(&hist2[pair][(k >> 16) & 0xff], 1);
    }
    __syncthreads();

    int B2, cnt2;
    hist_thresh(hist2[pair], lane, NTOPK - cnt1, B2, cnt2);
    const uint32_t T16 = ((uint32_t)B1 << 8) | (uint32_t)B2;

    #pragma unroll
    for (int i = 0; i < 32; i++) {
        const uint32_t k = __float_as_uint(v[i]);
        if ((k >> 16) >= T16) {
            const int p = atomicAdd(&cnt[pair], 1);
            if (p < CAP) {
                candK[pair][p] = k;
                candI[pair][p] = half * 1024 + (i >> 2) * 128 + (lane << 2) + (i & 3);
            }
        }
    }
    __syncthreads();
    const int n = cnt[pair];

    if (n > CAP) {
        for (int t = 0; t < NTOPK; t++) {
            uint32_t bk = 0; int bi = 0x7fffffff; int bs = -1;
            #pragma unroll
            for (int i = 0; i < 32; i++) {
                const uint32_t k = __float_as_uint(v[i]);
                const int idx = half * 1024 + (i >> 2) * 128 + (lane << 2) + (i & 3);
                if (k > bk || (k == bk && idx < bi)) { bk = k; bi = idx; bs = i; }
            }
            const int myBi = bi;
            #pragma unroll
            for (int off = 16; off > 0; off >>= 1) {
                const uint32_t ok = __shfl_xor_sync(FULL, bk, off);
                const int      oi = __shfl_xor_sync(FULL, bi, off);
                if (ok > bk || (ok == bk && oi < bi)) { bk = ok; bi = oi; }
            }
            if (myBi == bi && bs >= 0) {
                #pragma unroll
                for (int i = 0; i < 32; i++) if (i == bs) v[i] = __uint_as_float(0u);
            }
            if (lane == 0) { candK[pair][half * NTOPK + t] = bk; candI[pair][half * NTOPK + t] = bi; }
        }
    }
    __syncthreads();

    if (half == 0) {
        const int nSel = (n > CAP) ? (2 * NTOPK) : n;
        if (nSel <= 32) {
            unsigned long long key = 0ULL;
            if (lane < nSel)
                key = ((unsigned long long)candK[pair][lane] << 32)
                    | (uint32_t)(~candI[pair][lane]);
            #pragma unroll
            for (int k = 2; k <= 32; k <<= 1) {
                #pragma unroll
                for (int j = k >> 1; j > 0; j >>= 1) {
                    const unsigned long long o = __shfl_xor_sync(FULL, key, j);
                    const bool dirDesc = ((lane & k) == 0);
                    const bool lower   = ((lane & j) == 0);
                    const bool keepMax = (dirDesc == lower);
                    key = keepMax ? (key > o ? key : o) : (key < o ? key : o);
                }
            }
            if (lane < NTOPK) {
                topV[pair][lane]  = fkey_inv((uint32_t)(key >> 32));
                topIx[pair][lane] = (int)(~(uint32_t)key);
            }
        } else {
            for (int t = 0; t < NTOPK; t++) {
                uint32_t bk = 0; int bi = 0x7fffffff; int bp = -1;
                for (int p = lane; p < nSel; p += 32) {
                    const uint32_t xk = candK[pair][p];
                    const int      xi = candI[pair][p];
                    if (xk > bk || (xk == bk && xi < bi)) { bk = xk; bi = xi; bp = p; }
                }
                #pragma unroll
                for (int off = 16; off > 0; off >>= 1) {
                    const uint32_t ok = __shfl_xor_sync(FULL, bk, off);
                    const int      oi = __shfl_xor_sync(FULL, bi, off);
                    const int      op = __shfl_xor_sync(FULL, bp, off);
                    if (ok > bk || (ok == bk && oi < bi)) { bk = ok; bi = oi; bp = op; }
                }
                if (lane == 0) {
                    topV[pair][t]  = fkey_inv(bk);
                    topIx[pair][t] = bi;
                    candK[pair][bp] = 0;
                }
                __syncwarp();
            }
        }
    }
    __syncthreads();

    const float p  = (lane < NTOPK) ? __expf(topV[pair][lane] - m) / ssum : 0.f;
    const int   ix = (lane < NTOPK) ? topIx[pair][lane] : 0;
    const float* Vg = g_V + (size_t)b * NLK * NE + h * NHD + half * 32 + lane;
    float a = 0.f;
    #pragma unroll
    for (int j = 0; j < NTOPK; j++) {
        const float pj = __shfl_sync(FULL, p, j);
        const int   ij = __shfl_sync(FULL, ix, j);
        a = fmaf(pj, Vg[(size_t)ij * NE], a);
    }
    // rounded to tf32 so the out-projection can consume it directly
    g_O[(size_t)(b * NLQ + q) * NE + h * NHD + half * 32 + lane] = to_tf32(a);
}

// ----------------------------------------------------------------------------
extern "C" void kernel_launch(void* const* d_in, const int* in_sizes, int n_in,
                              void* d_out, int out_size)
{
    const float* q  = (const float*)d_in[0];
    const float* k  = (const float*)d_in[1];
    const float* v  = (const float*)d_in[2];
    const float* Wq = (const float*)d_in[3];
    const float* Wk = (const float*)d_in[4];
    const float* Wv = (const float*)d_in[5];
    const float* Wo = (const float*)d_in[6];
    const float* bo = (const float*)d_in[7];
    float* out = (float*)d_out;

    float *gQ, *gK, *gV, *gS, *gO, *gW;
    cudaGetSymbolAddress((void**)&gQ, g_Q);
    cudaGetSymbolAddress((void**)&gK, g_K);
    cudaGetSymbolAddress((void**)&gV, g_V);
    cudaGetSymbolAddress((void**)&gS, g_S);
    cudaGetSymbolAddress((void**)&gO, g_O);
    cudaGetSymbolAddress((void**)&gW, g_Wc);

    float* cq = gS + CQ_OFF;
    float* ck = gS + CK_OFF;
    float* cv = gS + CV_OFF;

    cudaFuncSetAttribute(gemm_ca, cudaFuncAttributeMaxDynamicSharedMemorySize,
                         GEMM_SMEM_BYTES);

    dim3 blk(256);

    // ---- pre-round inputs to tf32 (bit-identical to in-GEMM conversion) ----
    cvt4<<<256, 256>>>((float4*)(gW + 0 * 262144), (const float4*)Wq, 65536);
    cvt4<<<256, 256>>>((float4*)(gW + 1 * 262144), (const float4*)Wk, 65536);
    cvt4<<<256, 256>>>((float4*)(gW + 2 * 262144), (const float4*)Wv, 65536);
    cvt4<<<256, 256>>>((float4*)(gW + 3 * 262144), (const float4*)Wo, 65536);
    cvt4<<<2048, 256>>>((float4*)cq, (const float4*)q, 524288);
    cvt4<<<8192, 256>>>((float4*)ck, (const float4*)k, 2097152);
    cvt4<<<8192, 256>>>((float4*)cv, (const float4*)v, 2097152);

    // Q = q @ Wq^T  (output rounded to tf32 for the scores GEMM)
    gemm_ca<<<dim3(NE / 128, (NB * NLQ) / 128, 1), blk, GEMM_SMEM_BYTES>>>(
        cq, gW + 0 * 262144, gQ, NE, NE, NE, NE, 1.0f,
        0, 0, 0, 0, 0, 1, nullptr, nullptr, 0, 1);

    // K = k @ Wk^T  (rounded)
    gemm_ca<<<dim3(NE / 128, (NB * NLK) / 128, 1), blk, GEMM_SMEM_BYTES>>>(
        ck, gW + 1 * 262144, gK, NE, NE, NE, NE, 1.0f,
        0, 0, 0, 0, 0, 1, nullptr, nullptr, 0, 1);

    // V = v @ Wv^T  (full fp32: used directly by sparse AV)
    gemm_ca<<<dim3(NE / 128, (NB * NLK) / 128, 1), blk, GEMM_SMEM_BYTES>>>(
        cv, gW + 2 * 262144, gV, NE, NE, NE, NE, 1.0f,
        0, 0, 0, 0, 0, 1, nullptr, nullptr, 0, 0);

    // S[b,h] = (1/8) * Q_h @ K_h^T  (streaming stores; overwrites cq/ck/cv scratch)
    gemm_ca<<<dim3(NLK / 128, NLQ / 128, NB * NH), blk, GEMM_SMEM_BYTES>>>(
        gQ, gK, gS, NHD, NE, NE, NLK, 0.125f,
        (size_t)NLQ * NE, (size_t)NHD,
        (size_t)NLK * NE, (size_t)NHD,
        (size_t)NLQ * NLK, NH,
        nullptr, nullptr, 1, 0);

    // 2-warps-per-row radix top-20 + softmax + sparse AV (g_O rounded)
    topk_av<<<(NB * NH * NLQ) / 4, blk>>>();

    // out = O @ Wo^T + bo + q
    gemm_ca<<<dim3(NE / 128, (NB * NLQ) / 128, 1), blk, GEMM_SMEM_BYTES>>>(
        gO, gW + 3 * 262144, out, NE, NE, NE, NE, 1.0f,
        0, 0, 0, 0, 0, 1, bo, q, 0, 0);
}